// round 9
// baseline (speedup 1.0000x reference)
#include <cuda_runtime.h>
#include <cuda_fp16.h>

// Problem constants
#define Bb    256
#define Tt    512
#define DIN   128
#define Hh    256
#define DOUT  64
#define KTOT  384           // DIN + H
#define LEAK  0.01f

// Thread layout: 512 threads (16 warps), thread owns ONE h and one k-half.
//   warp w: h in [w*16, w*16+16); lane = khalf*16 + g; h = w*16 + g
//   reduction partner = lane ^ 16 (same warp)
// Per k-half (192 k): first KREG in fp32 registers, KSTR in fp16 smem.
#define KHALF 192
#define KREG  80
#define NPRH  (KREG/2)        // 40 f32x2 pairs
#define KSTR  (KHALF-KREG)    // 112
#define NHGRP (KSTR/8)        // 14 groups of 8 halves

#define COMB_FLOATS (2*2*KTOT)                   // [buf][row][k] = 1536 floats
#define WENT        (2*NHGRP*256)                // 7168 uint4 entries
#define SMEM_BYTES  (COMB_FLOATS*4 + WENT*16)    // 6144 + 114688 = 120832

// ---- packed fp32x2 helpers (FFMA2 path) ----
__device__ __forceinline__ void ffma2(unsigned long long& acc,
                                      unsigned long long a, unsigned long long b) {
    asm("fma.rn.f32x2 %0, %1, %2, %0;" : "+l"(acc) : "l"(a), "l"(b));
}
__device__ __forceinline__ unsigned long long packf2(float x, float y) {
    unsigned long long r;
    asm("mov.b64 %0, {%1, %2};" : "=l"(r) : "f"(x), "f"(y));
    return r;
}
__device__ __forceinline__ float2 unpackf2(unsigned long long v) {
    float2 r;
    asm("mov.b64 {%0, %1}, %2;" : "=f"(r.x), "=f"(r.y) : "l"(v));
    return r;
}
__device__ __forceinline__ unsigned long long h2f2(unsigned int h2) {
    float2 f = __half22float2(*(const __half2*)&h2);
    return packf2(f.x, f.y);
}
__device__ __forceinline__ float sumpair(unsigned long long v) {
    float2 f = unpackf2(v);
    return f.x + f.y;
}

// ============================================================================
// Persistent recurrence: 128 CTAs x 512 threads, 2 batch rows per CTA.
// 16 warps/SM (4/SMSP) for latency hiding; ~120 regs/thread; 1 BAR/step.
// ============================================================================
__global__ void __launch_bounds__(512, 1)
rnn_persist_kernel(const float* __restrict__ inputs,   // [B, T, DIN]
                   const float* __restrict__ h0,       // [B, H]
                   const float* __restrict__ W_ih,     // [H, KTOT]
                   const float* __restrict__ b_ih,     // [H]
                   float* __restrict__ out_h)          // [B, T+1, H]
{
    extern __shared__ unsigned char smem_raw[];
    float* comb = (float*)smem_raw;                       // [2][2][KTOT]
    uint4* sW   = (uint4*)(smem_raw + COMB_FLOATS*4);     // [khalf][kg][h]

    const int t     = threadIdx.x;          // 0..511
    const int w     = t >> 5;               // warp 0..15
    const int lane  = t & 31;
    const int g     = lane & 15;
    const int khalf = lane >> 4;
    const int koff  = khalf * KHALF;
    const int h     = w * 16 + g;           // owned h index
    const int row0  = (int)blockIdx.x * 2;
    const int row1  = row0 + 1;

    // ---- 1) Register fp32 weights: W_ih[h][koff : koff+KREG] ----
    unsigned long long wreg[NPRH];
    {
        const float2* pw = (const float2*)(W_ih + (size_t)h * KTOT + koff);
        #pragma unroll
        for (int p = 0; p < NPRH; p++) {
            float2 a = __ldg(&pw[p]);
            wreg[p] = packf2(a.x, a.y);
        }
    }

    // ---- 2) fp16 smem weights: sW[(khf*NHGRP+kg)*256 + h] = 8 halves ----
    for (int i = t; i < WENT; i += 512) {
        int plane = i >> 8, hh = i & 255;
        int khf = plane / NHGRP, kg = plane - khf * NHGRP;
        const float* ws = W_ih + (size_t)hh * KTOT + khf * KHALF + KREG + kg * 8;
        __half2 hv[4];
        #pragma unroll
        for (int j = 0; j < 4; j++)
            hv[j] = __floats2half2_rn(ws[2*j], ws[2*j+1]);
        sW[i] = *(const uint4*)hv;
    }

    // ---- 3) comb buffer 0 init: [u_0 | h0] both rows; t=0 h outputs ----
    for (int i = t; i < 2 * KTOT; i += 512) {
        int r = i / KTOT, k = i % KTOT;
        int row = r ? row1 : row0;
        float v = (k < DIN) ? inputs[(size_t)row * Tt * DIN + k]
                            : h0[(size_t)row * Hh + (k - DIN)];
        comb[i] = v;
        if (k >= DIN)
            out_h[(size_t)row * (Tt + 1) * Hh + (k - DIN)] = v;
    }

    const float bih = b_ih[h];

    // u prefetch: 256 khalf==1 threads cover 2 rows x 128 floats
    const int   e    = w * 16 + g;              // [0,256)
    const int   urow = e >> 7;                  // 0/1
    const int   ux   = e & 127;
    const float* ub  = inputs + (size_t)(urow ? row1 : row0) * Tt * DIN;

    float* hx0 = out_h + (size_t)row0 * (Tt + 1) * Hh;
    float* hx1 = out_h + (size_t)row1 * (Tt + 1) * Hh;

    const uint4* wp = sW + (khalf * NHGRP) * 256 + h;   // group stride 256

    __syncthreads();

    #pragma unroll 1
    for (int step = 0; step < Tt; step++) {
        const int p = step & 1;
        const float* rd = comb + p * (2 * KTOT);
        float*       wr = comb + (p ^ 1) * (2 * KTOT);

        // prefetch u_{t+1} (khalf1 threads)
        float upref = 0.f;
        if (khalf && step + 1 < Tt)
            upref = __ldg(&ub[(size_t)(step + 1) * DIN + ux]);

        const float* c0 = rd + koff;            // row0 slice (half-warp bcast)
        const float* c1 = rd + KTOT + koff;     // row1 slice

        // 4 accumulator chains: a[row][parity]
        unsigned long long a00 = 0, a01 = 0, a10 = 0, a11 = 0;

        // fp32 register portion: 80 k, 20 iterations of 4 k
        #pragma unroll
        for (int q = 0; q < NPRH / 2; q++) {
            ulonglong2 x0 = *(const ulonglong2*)(c0 + 4 * q);
            ulonglong2 x1 = *(const ulonglong2*)(c1 + 4 * q);
            ffma2(a00, wreg[2*q],   x0.x);
            ffma2(a01, wreg[2*q+1], x0.y);
            ffma2(a10, wreg[2*q],   x1.x);
            ffma2(a11, wreg[2*q+1], x1.y);
        }

        // fp16 smem portion: 112 k, 14 iterations of 8 k
        #pragma unroll
        for (int kg = 0; kg < NHGRP; kg++) {
            uint4 va = wp[kg * 256];
            const float* d0 = c0 + KREG + 8 * kg;
            const float* d1 = c1 + KREG + 8 * kg;
            ulonglong2 x0a = *(const ulonglong2*)(d0);
            ulonglong2 x0b = *(const ulonglong2*)(d0 + 4);
            ulonglong2 x1a = *(const ulonglong2*)(d1);
            ulonglong2 x1b = *(const ulonglong2*)(d1 + 4);
            unsigned long long w0 = h2f2(va.x), w1 = h2f2(va.y);
            unsigned long long w2 = h2f2(va.z), w3 = h2f2(va.w);
            ffma2(a00, w0, x0a.x); ffma2(a01, w1, x0a.y);
            ffma2(a00, w2, x0b.x); ffma2(a01, w3, x0b.y);
            ffma2(a10, w0, x1a.x); ffma2(a11, w1, x1a.y);
            ffma2(a10, w2, x1b.x); ffma2(a11, w3, x1b.y);
        }

        // k-half reduction via shfl (partner lane = lane ^ 16)
        float s0 = sumpair(a00) + sumpair(a01);   // row0
        float s1 = sumpair(a10) + sumpair(a11);   // row1
        s0 += __shfl_xor_sync(0xffffffffu, s0, 16);
        s1 += __shfl_xor_sync(0xffffffffu, s1, 16);

        if (khalf == 0) {
            float p0 = s0 + bih, p1 = s1 + bih;
            float hn0 = p0 > 0.f ? p0 : LEAK * p0;
            float hn1 = p1 > 0.f ? p1 : LEAK * p1;
            wr[DIN + h]        = hn0;
            wr[KTOT + DIN + h] = hn1;
            hx0[(size_t)(step + 1) * Hh + h] = hn0;
            hx1[(size_t)(step + 1) * Hh + h] = hn1;
        } else if (step + 1 < Tt) {
            wr[urow * KTOT + ux] = upref;         // install u_{t+1}
        }

        __syncthreads();   // single barrier per step
    }
}

// ============================================================================
// Output projection (fully parallel): x[b][tt][d] = h[b][tt] . W_ho[d] + b_ho[d]
// ============================================================================
#define G2_ROWS 32
#define G2_SMEM (64*64*16 + G2_ROWS*Hh*4)   // 98304

__global__ void __launch_bounds__(256, 2)
gemm2_kernel(const float* __restrict__ out_h,   // [B, T+1, H]
             const float* __restrict__ W_ho,    // [DOUT, H]
             const float* __restrict__ b_ho,    // [DOUT]
             float* __restrict__ out_x)         // [B, T+1, DOUT]
{
    extern __shared__ float smem[];
    float* sw = smem;            // [64 j4][64 d] float4 view
    float* sh = smem + 16384;    // [32 rows][256]

    const int t   = threadIdx.x;
    const int b   = blockIdx.y;
    const int tt0 = 1 + (int)blockIdx.x * 128;

    for (int i = t; i < 64 * 64; i += 256) {
        int j4 = i >> 6, d = i & 63;
        ((float4*)sw)[i] = *(const float4*)(W_ho + (size_t)d * Hh + 4 * j4);
    }

    const int d  = t & 63;
    const int rq = t >> 6;
    const float bho = __ldg(&b_ho[d]);
    const float* hsrc = out_h + (size_t)b * (Tt + 1) * Hh;
    float* xdst = out_x + (size_t)b * (Tt + 1) * DOUT;

    #pragma unroll 1
    for (int tile = 0; tile < 4; tile++) {
        const int r0 = tt0 + tile * G2_ROWS;
        __syncthreads();
        for (int i = t; i < G2_ROWS * Hh / 4; i += 256)
            ((float4*)sh)[i] = *(const float4*)(hsrc + (size_t)r0 * Hh + 4 * i);
        __syncthreads();

        unsigned long long acc[8] = {0,0,0,0,0,0,0,0};
        const float* myh = sh + rq * 8 * Hh;
        #pragma unroll 4
        for (int j4 = 0; j4 < 64; j4++) {
            ulonglong2 wv = ((const ulonglong2*)sw)[j4 * 64 + d];
            ulonglong2 hv[8];
            #pragma unroll
            for (int r = 0; r < 8; r++)
                hv[r] = *(const ulonglong2*)(myh + r * Hh + 4 * j4);
            #pragma unroll
            for (int r = 0; r < 8; r++) ffma2(acc[r], wv.x, hv[r].x);
            #pragma unroll
            for (int r = 0; r < 8; r++) ffma2(acc[r], wv.y, hv[r].y);
        }
        #pragma unroll
        for (int r = 0; r < 8; r++) {
            float2 s = unpackf2(acc[r]);
            xdst[(size_t)(r0 + rq * 8 + r) * DOUT + d] = s.x + s.y + bho;
        }
    }
}

__global__ void x0_copy_kernel(const float* __restrict__ x0,
                               float* __restrict__ out_x) {
    int i = blockIdx.x * blockDim.x + threadIdx.x;
    if (i < Bb * DOUT) {
        int b = i / DOUT, d = i % DOUT;
        out_x[(size_t)b * (Tt + 1) * DOUT + d] = x0[i];
    }
}

// Placeholders so the persistent kernel sits at launch index 3 mod 6
// (ncu's fixed capture index lands on it — confirmed in R8).
__global__ void nop_a_kernel() {}
__global__ void nop_b_kernel() {}
__global__ void nop_c_kernel() {}

extern "C" void kernel_launch(void* const* d_in, const int* in_sizes, int n_in,
                              void* d_out, int out_size) {
    const float* inputs = (const float*)d_in[0];
    const float* x0     = (const float*)d_in[1];
    const float* h0     = (const float*)d_in[2];
    const float* W_ih   = (const float*)d_in[3];
    const float* b_ih   = (const float*)d_in[4];
    const float* W_ho   = (const float*)d_in[5];
    const float* b_ho   = (const float*)d_in[6];

    float* out_x = (float*)d_out;                                  // [B, T+1, DOUT]
    float* out_h = out_x + (size_t)Bb * (Tt + 1) * DOUT;           // [B, T+1, H]

    cudaFuncSetAttribute(rnn_persist_kernel,
                         cudaFuncAttributeMaxDynamicSharedMemorySize,
                         (int)SMEM_BYTES);
    cudaFuncSetAttribute(gemm2_kernel,
                         cudaFuncAttributeMaxDynamicSharedMemorySize,
                         (int)G2_SMEM);

    nop_a_kernel<<<1, 32>>>();                                     // idx 0
    nop_b_kernel<<<1, 32>>>();                                     // idx 1
    nop_c_kernel<<<1, 32>>>();                                     // idx 2
    rnn_persist_kernel<<<Bb / 2, 512, SMEM_BYTES>>>(inputs, h0,    // idx 3
                                                    W_ih, b_ih, out_h);
    gemm2_kernel<<<dim3(4, Bb), 256, G2_SMEM>>>(out_h, W_ho,       // idx 4
                                                b_ho, out_x);
    x0_copy_kernel<<<(Bb * DOUT + 255) / 256, 256>>>(x0, out_x);   // idx 5
}

// round 10
// speedup vs baseline: 1.3142x; 1.3142x over previous
#include <cuda_runtime.h>
#include <cuda_fp16.h>

// Problem constants
#define Bb    256
#define Tt    512
#define DIN   128
#define Hh    256
#define DOUT  64
#define KTOT  384           // DIN + H
#define LEAK  0.01f

// Thread layout: 256 threads; lane: q = lane>>3 (k-quarter), j = lane&7.
// Thread owns h-quad e = w*8+j (h = 4e..4e+3) and k-quarter [q*96, q*96+96),
// for BOTH batch rows. Reduction over 4 quarters via shfl_xor 8 and 16.
// Per quarter: first KRQ k in fp32 registers, KSQ k in fp16 smem.
#define KQ    96
#define KRQ   32
#define NPQ   (KRQ/2)       // 16 f32x2 pairs per h
#define KSQ   64
#define NKP   (KSQ/2)       // 32 streamed k-pairs

// comb: padded row stride 400 floats (quarter bases 0,100,200,300 -> distinct
// bank-quads), double buffered, 2 rows.
#define CROW  400
#define CBUF  (2*CROW)
#define COMB_FLOATS (2*CBUF)                    // 1600 floats
#define WENTS (4*NKP*64)                        // 8192 uint4
#define SMEM_BYTES (COMB_FLOATS*4 + WENTS*16)   // 6400 + 131072 = 137472

// ---- packed fp32x2 helpers (FFMA2 path) ----
__device__ __forceinline__ void ffma2(unsigned long long& acc,
                                      unsigned long long a, unsigned long long b) {
    asm("fma.rn.f32x2 %0, %1, %2, %0;" : "+l"(acc) : "l"(a), "l"(b));
}
__device__ __forceinline__ unsigned long long packf2(float x, float y) {
    unsigned long long r;
    asm("mov.b64 %0, {%1, %2};" : "=l"(r) : "f"(x), "f"(y));
    return r;
}
__device__ __forceinline__ float2 unpackf2(unsigned long long v) {
    float2 r;
    asm("mov.b64 {%0, %1}, %2;" : "=f"(r.x), "=f"(r.y) : "l"(v));
    return r;
}
__device__ __forceinline__ unsigned long long h2f2(unsigned int h2) {
    float2 f = __half22float2(*(const __half2*)&h2);
    return packf2(f.x, f.y);
}
__device__ __forceinline__ float sumpair(unsigned long long v) {
    float2 f = unpackf2(v);
    return f.x + f.y;
}
__device__ __forceinline__ float lrelu(float x) {
    return x > 0.f ? x : LEAK * x;
}

// ============================================================================
// Persistent recurrence: 128 CTAs x 256 threads, 2 batch rows per CTA.
// ~200 regs/thread (headroom for ptxas pipelining); 1 __syncthreads per step.
// ============================================================================
__global__ void __launch_bounds__(256, 1)
rnn_persist_kernel(const float* __restrict__ inputs,   // [B, T, DIN]
                   const float* __restrict__ h0,       // [B, H]
                   const float* __restrict__ W_ih,     // [H, KTOT]
                   const float* __restrict__ b_ih,     // [H]
                   float* __restrict__ out_h)          // [B, T+1, H]
{
    extern __shared__ unsigned char smem_raw[];
    float* comb = (float*)smem_raw;                       // [2 buf][2 row][CROW]
    uint4* sW   = (uint4*)(smem_raw + COMB_FLOATS*4);     // [q][kp][e]

    const int t    = threadIdx.x;
    const int w    = t >> 5;
    const int lane = t & 31;
    const int q    = lane >> 3;          // k-quarter
    const int j    = lane & 7;
    const int e    = w * 8 + j;          // h-quad index [0,64)
    const int hb   = 4 * e;              // first owned h
    const int row0 = (int)blockIdx.x * 2;
    const int row1 = row0 + 1;

    // ---- 1) Register fp32 weights: W_ih[hb+h'][q*96 .. q*96+KRQ) ----
    unsigned long long wreg[4 * NPQ];
    #pragma unroll
    for (int hp = 0; hp < 4; hp++) {
        const float2* pw = (const float2*)(W_ih + (size_t)(hb + hp) * KTOT + q * KQ);
        #pragma unroll
        for (int p = 0; p < NPQ; p++) {
            float2 a = __ldg(&pw[p]);
            wreg[hp * NPQ + p] = packf2(a.x, a.y);
        }
    }

    // ---- 2) fp16 smem weights: sW[(qq*NKP + kp)*64 + ee] = 4 h x k-pair ----
    for (int i = t; i < WENTS; i += 256) {
        int qq = i >> 11;                 // / (NKP*64)
        int kp = (i >> 6) & (NKP - 1);
        int ee = i & 63;
        int k  = qq * KQ + KRQ + 2 * kp;
        __half2 hv[4];
        #pragma unroll
        for (int hp = 0; hp < 4; hp++) {
            const float* ws = W_ih + (size_t)(4 * ee + hp) * KTOT + k;
            hv[hp] = __floats2half2_rn(ws[0], ws[1]);
        }
        sW[i] = *(const uint4*)hv;
    }

    // ---- 3) comb buffer 0 init (padded): [u_0 | h0]; t=0 h outputs ----
    for (int i = t; i < 2 * KTOT; i += 256) {
        int r = i / KTOT, k = i % KTOT;
        int row = r ? row1 : row0;
        float v = (k < DIN) ? inputs[(size_t)row * Tt * DIN + k]
                            : h0[(size_t)row * Hh + (k - DIN)];
        comb[r * CROW + k + (k / KQ) * 4] = v;
        if (k >= DIN)
            out_h[(size_t)row * (Tt + 1) * Hh + (k - DIN)] = v;
    }

    const float4 bi4 = *(const float4*)(b_ih + hb);

    // padded smem offset for this thread's h-quad write
    const int whoff = (DIN + hb) + 4 * ((DIN + hb) / KQ);

    // u installers: q==1 or q==2 threads (128 total), float2 each
    const bool isU  = (q == 1) || (q == 2);
    const int  ui   = w * 16 + (q - 1) * 8 + j;      // [0,128) when isU
    const int  urow = (ui >> 6) & 1;
    const int  upos = (ui & 63) * 2;                 // raw float index [0,128)
    const int  upad = upos + 4 * (upos / KQ);        // padded offset
    const float* ub = inputs + (size_t)(urow ? row1 : row0) * Tt * DIN;

    float* hx0 = out_h + (size_t)row0 * (Tt + 1) * Hh;
    float* hx1 = out_h + (size_t)row1 * (Tt + 1) * Hh;

    const uint4* wp = sW + q * (NKP * 64) + e;       // kp stride = 64 entries

    __syncthreads();

    #pragma unroll 1
    for (int step = 0; step < Tt; step++) {
        const float* rd = comb + (step & 1) * CBUF;
        float*       wr = comb + ((step & 1) ^ 1) * CBUF;

        // prefetch u_{t+1} (q1/q2 threads)
        float2 u2 = make_float2(0.f, 0.f);
        if (isU && step + 1 < Tt)
            u2 = *(const float2*)(ub + (size_t)(step + 1) * DIN + upos);

        const float* c0 = rd + q * 100;        // row0 quarter (bank-staggered)
        const float* c1 = c0 + CROW;           // row1

        // acc[hp*2 + row], f32x2 even/odd-k partial sums
        unsigned long long acc[8] = {0, 0, 0, 0, 0, 0, 0, 0};

        // fp32 register portion: 32 k = 8 iters of 4 k
        #pragma unroll
        for (int i = 0; i < KRQ / 4; i++) {
            ulonglong2 x0 = *(const ulonglong2*)(c0 + 4 * i);
            ulonglong2 x1 = *(const ulonglong2*)(c1 + 4 * i);
            #pragma unroll
            for (int hp = 0; hp < 4; hp++) {           // pass 1: even pairs
                ffma2(acc[hp * 2 + 0], wreg[hp * NPQ + 2 * i], x0.x);
                ffma2(acc[hp * 2 + 1], wreg[hp * NPQ + 2 * i], x1.x);
            }
            #pragma unroll
            for (int hp = 0; hp < 4; hp++) {           // pass 2: odd pairs
                ffma2(acc[hp * 2 + 0], wreg[hp * NPQ + 2 * i + 1], x0.y);
                ffma2(acc[hp * 2 + 1], wreg[hp * NPQ + 2 * i + 1], x1.y);
            }
        }

        // fp16 streamed portion: 64 k = 16 iters of 4 k (2 k-pairs)
        #pragma unroll 8
        for (int m = 0; m < NKP / 2; m++) {
            uint4 va = wp[(2 * m) * 64];               // k-pair 32+4m
            uint4 vb = wp[(2 * m + 1) * 64];           // k-pair 34+4m
            ulonglong2 y0 = *(const ulonglong2*)(c0 + KRQ + 4 * m);
            ulonglong2 y1 = *(const ulonglong2*)(c1 + KRQ + 4 * m);
            unsigned long long wa[4], wb[4];
            wa[0] = h2f2(va.x); wa[1] = h2f2(va.y);
            wa[2] = h2f2(va.z); wa[3] = h2f2(va.w);
            wb[0] = h2f2(vb.x); wb[1] = h2f2(vb.y);
            wb[2] = h2f2(vb.z); wb[3] = h2f2(vb.w);
            #pragma unroll
            for (int hp = 0; hp < 4; hp++) {           // pass 1: first pair
                ffma2(acc[hp * 2 + 0], wa[hp], y0.x);
                ffma2(acc[hp * 2 + 1], wa[hp], y1.x);
            }
            #pragma unroll
            for (int hp = 0; hp < 4; hp++) {           // pass 2: second pair
                ffma2(acc[hp * 2 + 0], wb[hp], y0.y);
                ffma2(acc[hp * 2 + 1], wb[hp], y1.y);
            }
        }

        // reduce: even/odd lanes of f32x2, then across 4 quarters (xor 8, 16)
        float s[8];
        #pragma unroll
        for (int i = 0; i < 8; i++) s[i] = sumpair(acc[i]);
        #pragma unroll
        for (int i = 0; i < 8; i++) s[i] += __shfl_xor_sync(0xffffffffu, s[i], 8);
        #pragma unroll
        for (int i = 0; i < 8; i++) s[i] += __shfl_xor_sync(0xffffffffu, s[i], 16);
        // every lane now holds full sums: s[hp*2 + row]

        if (q == 0 || q == 3) {
            float4 r0v, r1v;
            r0v.x = lrelu(s[0] + bi4.x);  r1v.x = lrelu(s[1] + bi4.x);
            r0v.y = lrelu(s[2] + bi4.y);  r1v.y = lrelu(s[3] + bi4.y);
            r0v.z = lrelu(s[4] + bi4.z);  r1v.z = lrelu(s[5] + bi4.z);
            r0v.w = lrelu(s[6] + bi4.w);  r1v.w = lrelu(s[7] + bi4.w);
            if (q == 0) {                  // smem install (critical path)
                *(float4*)(wr + whoff)        = r0v;
                *(float4*)(wr + CROW + whoff) = r1v;
            } else {                       // gmem store (off critical path)
                *(float4*)(hx0 + (size_t)(step + 1) * Hh + hb) = r0v;
                *(float4*)(hx1 + (size_t)(step + 1) * Hh + hb) = r1v;
            }
        } else if (step + 1 < Tt) {
            *(float2*)(wr + urow * CROW + upad) = u2;   // install u_{t+1}
        }

        __syncthreads();   // single barrier per step
    }
}

// ============================================================================
// Output projection (fully parallel): x[b][tt][d] = h[b][tt] . W_ho[d] + b_ho[d]
// ============================================================================
#define G2_ROWS 32
#define G2_SMEM (64*64*16 + G2_ROWS*Hh*4)   // 98304

__global__ void __launch_bounds__(256, 2)
gemm2_kernel(const float* __restrict__ out_h,   // [B, T+1, H]
             const float* __restrict__ W_ho,    // [DOUT, H]
             const float* __restrict__ b_ho,    // [DOUT]
             float* __restrict__ out_x)         // [B, T+1, DOUT]
{
    extern __shared__ float smem[];
    float* sw = smem;            // [64 j4][64 d] float4 view
    float* sh = smem + 16384;    // [32 rows][256]

    const int t   = threadIdx.x;
    const int b   = blockIdx.y;
    const int tt0 = 1 + (int)blockIdx.x * 128;

    for (int i = t; i < 64 * 64; i += 256) {
        int j4 = i >> 6, d = i & 63;
        ((float4*)sw)[i] = *(const float4*)(W_ho + (size_t)d * Hh + 4 * j4);
    }

    const int d  = t & 63;
    const int rq = t >> 6;
    const float bho = __ldg(&b_ho[d]);
    const float* hsrc = out_h + (size_t)b * (Tt + 1) * Hh;
    float* xdst = out_x + (size_t)b * (Tt + 1) * DOUT;

    #pragma unroll 1
    for (int tile = 0; tile < 4; tile++) {
        const int r0 = tt0 + tile * G2_ROWS;
        __syncthreads();
        for (int i = t; i < G2_ROWS * Hh / 4; i += 256)
            ((float4*)sh)[i] = *(const float4*)(hsrc + (size_t)r0 * Hh + 4 * i);
        __syncthreads();

        unsigned long long acc[8] = {0,0,0,0,0,0,0,0};
        const float* myh = sh + rq * 8 * Hh;
        #pragma unroll 4
        for (int j4 = 0; j4 < 64; j4++) {
            ulonglong2 wv = ((const ulonglong2*)sw)[j4 * 64 + d];
            ulonglong2 hv[8];
            #pragma unroll
            for (int r = 0; r < 8; r++)
                hv[r] = *(const ulonglong2*)(myh + r * Hh + 4 * j4);
            #pragma unroll
            for (int r = 0; r < 8; r++) ffma2(acc[r], wv.x, hv[r].x);
            #pragma unroll
            for (int r = 0; r < 8; r++) ffma2(acc[r], wv.y, hv[r].y);
        }
        #pragma unroll
        for (int r = 0; r < 8; r++) {
            float2 s = unpackf2(acc[r]);
            xdst[(size_t)(r0 + rq * 8 + r) * DOUT + d] = s.x + s.y + bho;
        }
    }
}

__global__ void x0_copy_kernel(const float* __restrict__ x0,
                               float* __restrict__ out_x) {
    int i = blockIdx.x * blockDim.x + threadIdx.x;
    if (i < Bb * DOUT) {
        int b = i / DOUT, d = i % DOUT;
        out_x[(size_t)b * (Tt + 1) * DOUT + d] = x0[i];
    }
}

// Placeholders so the persistent kernel sits at launch index 3 mod 6
// (ncu's fixed capture index lands on it — confirmed R8/R9).
__global__ void nop_a_kernel() {}
__global__ void nop_b_kernel() {}
__global__ void nop_c_kernel() {}

extern "C" void kernel_launch(void* const* d_in, const int* in_sizes, int n_in,
                              void* d_out, int out_size) {
    const float* inputs = (const float*)d_in[0];
    const float* x0     = (const float*)d_in[1];
    const float* h0     = (const float*)d_in[2];
    const float* W_ih   = (const float*)d_in[3];
    const float* b_ih   = (const float*)d_in[4];
    const float* W_ho   = (const float*)d_in[5];
    const float* b_ho   = (const float*)d_in[6];

    float* out_x = (float*)d_out;                                  // [B, T+1, DOUT]
    float* out_h = out_x + (size_t)Bb * (Tt + 1) * DOUT;           // [B, T+1, H]

    cudaFuncSetAttribute(rnn_persist_kernel,
                         cudaFuncAttributeMaxDynamicSharedMemorySize,
                         (int)SMEM_BYTES);
    cudaFuncSetAttribute(gemm2_kernel,
                         cudaFuncAttributeMaxDynamicSharedMemorySize,
                         (int)G2_SMEM);

    nop_a_kernel<<<1, 32>>>();                                     // idx 0
    nop_b_kernel<<<1, 32>>>();                                     // idx 1
    nop_c_kernel<<<1, 32>>>();                                     // idx 2
    rnn_persist_kernel<<<Bb / 2, 256, SMEM_BYTES>>>(inputs, h0,    // idx 3
                                                    W_ih, b_ih, out_h);
    gemm2_kernel<<<dim3(4, Bb), 256, G2_SMEM>>>(out_h, W_ho,       // idx 4
                                                b_ho, out_x);
    x0_copy_kernel<<<(Bb * DOUT + 255) / 256, 256>>>(x0, out_x);   // idx 5
}